// round 11
// baseline (speedup 1.0000x reference)
#include <cuda_runtime.h>
#include <cuda_fp16.h>
#include <cstdint>
#include <math.h>

#define LQ 8192
#define LK 8192
#define DIM 128
#define KCH 8
#define SCALE 0.08838834764831845f  // 1/sqrt(128)

#define STRQ 136  // fp16 elems per smem row, 128-wide tiles (272B, conflict-free)
#define STRP 72   // fp16 elems per smem row, 64-wide tiles (144B)

// ---------------- device scratch ----------------
__device__ __half g_qh[(size_t)LQ * DIM];
__device__ __half g_kh[(size_t)LK * DIM];
__device__ __half g_vth[(size_t)DIM * LK];          // V^T [d][k]
__device__ float g_lpart[(size_t)LQ * 64];
__device__ float g_il[LQ];
__device__ float g_opart[(size_t)KCH * LQ * DIM];

// ---------------- helpers ----------------
__device__ __forceinline__ uint32_t smem_u32(const void* p) {
    uint32_t a;
    asm("{ .reg .u64 t; cvta.to.shared.u64 t, %1; cvt.u32.u64 %0, t; }" : "=r"(a) : "l"(p));
    return a;
}
__device__ __forceinline__ void ldsm4(uint32_t (&r)[4], uint32_t addr) {
    asm volatile("ldmatrix.sync.aligned.m8n8.x4.shared.b16 {%0,%1,%2,%3}, [%4];"
        : "=r"(r[0]), "=r"(r[1]), "=r"(r[2]), "=r"(r[3]) : "r"(addr));
}
__device__ __forceinline__ void mma16816(float (&c)[4], const uint32_t (&a)[4],
                                         uint32_t b0, uint32_t b1) {
    asm volatile("mma.sync.aligned.m16n8k16.row.col.f32.f16.f16.f32 "
        "{%0,%1,%2,%3}, {%4,%5,%6,%7}, {%8,%9}, {%0,%1,%2,%3};"
        : "+f"(c[0]), "+f"(c[1]), "+f"(c[2]), "+f"(c[3])
        : "r"(a[0]), "r"(a[1]), "r"(a[2]), "r"(a[3]), "r"(b0), "r"(b1));
}
__device__ __forceinline__ void cpasync16(uint32_t dst, const void* src) {
    asm volatile("cp.async.cg.shared.global [%0], [%1], 16;" :: "r"(dst), "l"(src));
}
#define CP_COMMIT() asm volatile("cp.async.commit_group;" ::: "memory")
#define CP_WAIT(N)  asm volatile("cp.async.wait_group %0;" :: "n"(N) : "memory")
__device__ __forceinline__ uint32_t h2u(__half2 h) { return *reinterpret_cast<uint32_t*>(&h); }

// ---------------------------------------------------------------------------
// prep: fp32 -> fp16 (Q prescaled, K, V transposed)
// ---------------------------------------------------------------------------
__global__ __launch_bounds__(256) void prep_kernel(const float* __restrict__ Q,
                                                   const float* __restrict__ K,
                                                   const float* __restrict__ V) {
    size_t i = (size_t)blockIdx.x * 256 + threadIdx.x;
    g_qh[i] = __float2half_rn(Q[i] * SCALE);
    g_kh[i] = __float2half_rn(K[i]);
    size_t kr = i >> 7, d = i & 127;
    g_vth[d * LK + kr] = __float2half_rn(V[i]);
}

// ---------------------------------------------------------------------------
// Kernel A1: row partial sums of exp(Qs @ K^T). 64m x 128n per CTA. NO store.
// Same k16 accumulation order as A2's QK -> identical e values.
// ---------------------------------------------------------------------------
__global__ __launch_bounds__(256, 2) void qk_sums_kernel() {
    extern __shared__ __align__(16) char smem[];
    __half* Qh = (__half*)smem;            // [64][STRQ]
    __half* Kh = Qh + 64 * STRQ;           // [128][STRQ]

    const int tid = threadIdx.x, lane = tid & 31, wid = tid >> 5;
    const int m0 = blockIdx.y * 64, n0 = blockIdx.x * 128;

    const uint32_t qhb = smem_u32(Qh), khb = smem_u32(Kh);

#pragma unroll
    for (int i = 0; i < 4; i++) {
        int idx = i * 256 + tid;
        int row = idx >> 4, seg = idx & 15;
        cpasync16(qhb + row * 272 + seg * 16, g_qh + (size_t)(m0 + row) * DIM + seg * 8);
    }
#pragma unroll
    for (int i = 0; i < 8; i++) {
        int idx = i * 256 + tid;
        int row = idx >> 4, seg = idx & 15;
        cpasync16(khb + row * 272 + seg * 16, g_kh + (size_t)(n0 + row) * DIM + seg * 8);
    }
    CP_COMMIT();
    CP_WAIT(0);
    __syncthreads();

    const int wm = (wid >> 2) * 32, wn = (wid & 3) * 32;
    float c[2][4][4];
#pragma unroll
    for (int mi = 0; mi < 2; mi++)
#pragma unroll
        for (int nj = 0; nj < 4; nj++)
#pragma unroll
            for (int e = 0; e < 4; e++) c[mi][nj][e] = 0.f;

    const int arow = lane & 15;
    const int acol = (lane >> 4) * 8;

#pragma unroll
    for (int k16 = 0; k16 < 8; k16++) {
        const int kc = k16 * 16 + acol;
        uint32_t a[2][4], b[2][4];
#pragma unroll
        for (int nj = 0; nj < 2; nj++)
            ldsm4(b[nj], khb + ((wn + nj * 16 + arow) * STRQ + kc) * 2);
#pragma unroll
        for (int mi = 0; mi < 2; mi++)
            ldsm4(a[mi], qhb + ((wm + mi * 16 + arow) * STRQ + kc) * 2);
#pragma unroll
        for (int mi = 0; mi < 2; mi++)
#pragma unroll
            for (int n8 = 0; n8 < 4; n8++)
                mma16816(c[mi][n8], a[mi], b[n8 >> 1][n8 & 1], b[n8 >> 1][(n8 & 1) + 2]);
    }

#pragma unroll
    for (int mi = 0; mi < 2; mi++)
#pragma unroll
        for (int n8 = 0; n8 < 4; n8++)
#pragma unroll
            for (int e = 0; e < 4; e++) c[mi][n8][e] = __expf(c[mi][n8][e]);

    __syncthreads();
    float* rs = (float*)smem;  // [64][4]
#pragma unroll
    for (int mi = 0; mi < 2; mi++) {
        float v0 = 0.f, v1 = 0.f;
#pragma unroll
        for (int n8 = 0; n8 < 4; n8++) {
            v0 += c[mi][n8][0] + c[mi][n8][1];
            v1 += c[mi][n8][2] + c[mi][n8][3];
        }
        v0 += __shfl_xor_sync(0xffffffffu, v0, 1);
        v0 += __shfl_xor_sync(0xffffffffu, v0, 2);
        v1 += __shfl_xor_sync(0xffffffffu, v1, 1);
        v1 += __shfl_xor_sync(0xffffffffu, v1, 2);
        if ((lane & 3) == 0) {
            int r = wm + mi * 16 + (lane >> 2);
            rs[r * 4 + (wid & 3)] = v0;
            rs[(r + 8) * 4 + (wid & 3)] = v1;
        }
    }
    __syncthreads();
    if (tid < 64) {
        float s = rs[tid * 4] + rs[tid * 4 + 1] + rs[tid * 4 + 2] + rs[tid * 4 + 3];
        g_lpart[(size_t)(m0 + tid) * 64 + blockIdx.x] = s;
    }
}

// ---------------------------------------------------------------------------
// Kernel B: l = sum of partials (fixed order), store 1/l.
// ---------------------------------------------------------------------------
__global__ __launch_bounds__(256) void lred_kernel() {
    const int row = blockIdx.x * 256 + threadIdx.x;
    const float4* p = (const float4*)(g_lpart + (size_t)row * 64);
    float s = 0.f;
#pragma unroll
    for (int i = 0; i < 16; i++) {
        float4 v = p[i];
        s += v.x + v.y + v.z + v.w;
    }
    g_il[row] = 1.0f / s;
}

// ---------------------------------------------------------------------------
// Kernel A2 (fused): recompute S = Qs@K^T per 64q x 64n tile, p = exp(s)*il,
// write att (only att traffic), stage p in fp16 smem, O += p @ V.
// CTA 64q x k-chunk 1024 (16 iters). K/V double-buffered cp.async (dist 1).
// grid (KCH, LQ/64). 2 CTAs/SM.
// ---------------------------------------------------------------------------
__global__ __launch_bounds__(256, 2) void fused_kernel(float* __restrict__ att) {
    extern __shared__ __align__(16) char smem[];
    // layout (bytes): Qs 17408 | Ks 2x17408 | Vs 2x18432 | Ps 9216  = 98304
    __half* Qs = (__half*)smem;
    const uint32_t qb = smem_u32(Qs);
    const uint32_t kbb = qb + 17408;
    const uint32_t vbb = kbb + 34816;
    const uint32_t pbB = vbb + 36864;
    const int KBUF = 17408, VBUF = 18432;

    const int tid = threadIdx.x, lane = tid & 31, wid = tid >> 5;
    const int q0 = blockIdx.y * 64;
    const int kbase = blockIdx.x * (LK / KCH);

    const int arow = lane & 15, acol = (lane >> 4) * 8;
    const int r0 = lane >> 2, c0 = (lane & 3) * 2;
    // QK partition: warp = 16q x 32n
    const int wm = (wid >> 1) * 16, wn = (wid & 1) * 32;
    // PV partition: warp = 16q x 64d
    const int wm2 = (wid & 3) * 16, wd = (wid >> 2) * 64;

    const float il0 = g_il[q0 + wm + r0];
    const float il1 = g_il[q0 + wm + r0 + 8];

    // prologue: Q + K(0) + V(0), one group
#pragma unroll
    for (int i = 0; i < 4; i++) {
        int idx = i * 256 + tid;
        int row = idx >> 4, seg = idx & 15;
        cpasync16(qb + row * 272 + seg * 16, g_qh + (size_t)(q0 + row) * DIM + seg * 8);
    }
#pragma unroll
    for (int i = 0; i < 4; i++) {
        int idx = i * 256 + tid;
        int row = idx >> 4, seg = idx & 15;
        cpasync16(kbb + row * 272 + seg * 16, g_kh + (size_t)(kbase + row) * DIM + seg * 8);
    }
#pragma unroll
    for (int i = 0; i < 4; i++) {
        int idx = i * 256 + tid;
        int row = idx >> 3, seg = idx & 7;
        cpasync16(vbb + row * 144 + seg * 16, g_vth + (size_t)row * LK + kbase + seg * 8);
    }
    CP_COMMIT();

    float o[8][4];
#pragma unroll
    for (int nj = 0; nj < 8; nj++)
#pragma unroll
        for (int e = 0; e < 4; e++) o[nj][e] = 0.f;

    for (int t = 0; t < 16; t++) {
        CP_WAIT(0);           // K(t), V(t) resident
        __syncthreads();      // all warps finished iter t-1 (buffers + Ps free)

        // prefetch K(t+1), V(t+1) into the other buffer
        if (t < 15) {
            const int ktn = kbase + (t + 1) * 64;
            const uint32_t kdst = kbb + ((t + 1) & 1) * KBUF;
            const uint32_t vdst = vbb + ((t + 1) & 1) * VBUF;
#pragma unroll
            for (int i = 0; i < 4; i++) {
                int idx = i * 256 + tid;
                int row = idx >> 4, seg = idx & 15;
                cpasync16(kdst + row * 272 + seg * 16,
                          g_kh + (size_t)(ktn + row) * DIM + seg * 8);
            }
#pragma unroll
            for (int i = 0; i < 4; i++) {
                int idx = i * 256 + tid;
                int row = idx >> 3, seg = idx & 7;
                cpasync16(vdst + row * 144 + seg * 16,
                          g_vth + (size_t)row * LK + ktn + seg * 8);
            }
        }
        CP_COMMIT();

        const uint32_t kcur = kbb + (t & 1) * KBUF;
        const uint32_t vcur = vbb + (t & 1) * VBUF;
        const int kt0 = kbase + t * 64;

        // --- QK: c = Qs[64][128] @ K(t)[64][128]^T, warp tile 16q x 32n ---
        float c[4][4];
#pragma unroll
        for (int n8 = 0; n8 < 4; n8++)
#pragma unroll
            for (int e = 0; e < 4; e++) c[n8][e] = 0.f;

#pragma unroll
        for (int k16 = 0; k16 < 8; k16++) {
            const int kc = k16 * 16 + acol;
            uint32_t a[4], b0[4], b1[4];
            ldsm4(a, qb + ((wm + arow) * STRQ + kc) * 2);
            ldsm4(b0, kcur + ((wn + arow) * STRQ + kc) * 2);
            ldsm4(b1, kcur + ((wn + 16 + arow) * STRQ + kc) * 2);
            mma16816(c[0], a, b0[0], b0[2]);
            mma16816(c[1], a, b0[1], b0[3]);
            mma16816(c[2], a, b1[0], b1[2]);
            mma16816(c[3], a, b1[1], b1[3]);
        }

        // --- exp, normalize, write att, stage P (fp16) ---
#pragma unroll
        for (int n8 = 0; n8 < 4; n8++) {
            c[n8][0] = __expf(c[n8][0]) * il0;
            c[n8][1] = __expf(c[n8][1]) * il0;
            c[n8][2] = __expf(c[n8][2]) * il1;
            c[n8][3] = __expf(c[n8][3]) * il1;
        }
#pragma unroll
        for (int n8 = 0; n8 < 4; n8++) {
            size_t row = (size_t)(q0 + wm + r0);
            size_t col = (size_t)(kt0 + wn + n8 * 8 + c0);
            *(float2*)(att + row * LK + col) = make_float2(c[n8][0], c[n8][1]);
            *(float2*)(att + (row + 8) * LK + col) = make_float2(c[n8][2], c[n8][3]);
            uint32_t po = pbB + ((wm + r0) * STRP + wn + n8 * 8 + c0) * 2;
            uint32_t h01 = h2u(__floats2half2_rn(c[n8][0], c[n8][1]));
            uint32_t h23 = h2u(__floats2half2_rn(c[n8][2], c[n8][3]));
            asm volatile("st.shared.b32 [%0], %1;" :: "r"(po), "r"(h01) : "memory");
            asm volatile("st.shared.b32 [%0], %1;" :: "r"(po + STRP * 2 * 8), "r"(h23) : "memory");
        }
        __syncthreads();      // P visible to all warps

        // --- PV: o += P[64][64] @ V(t)^T, warp tile 16q x 64d ---
#pragma unroll
        for (int k16 = 0; k16 < 4; k16++) {
            const int kc = k16 * 16 + acol;
            uint32_t ap[4];
            ldsm4(ap, pbB + ((wm2 + arow) * STRP + kc) * 2);
#pragma unroll
            for (int g = 0; g < 4; g++) {
                uint32_t bv[4];
                ldsm4(bv, vcur + ((wd + g * 16 + arow) * STRP + kc) * 2);
                mma16816(o[2 * g], ap, bv[0], bv[2]);
                mma16816(o[2 * g + 1], ap, bv[1], bv[3]);
            }
        }
    }

    float* op = g_opart + (size_t)blockIdx.x * ((size_t)LQ * DIM);
#pragma unroll
    for (int nj = 0; nj < 8; nj++) {
        size_t row = (size_t)(q0 + wm2 + r0);
        size_t col = (size_t)(wd + nj * 8 + c0);
        *(float2*)(op + row * DIM + col) = make_float2(o[nj][0], o[nj][1]);
        *(float2*)(op + (row + 8) * DIM + col) = make_float2(o[nj][2], o[nj][3]);
    }
}

// ---------------------------------------------------------------------------
// Kernel D: reduce KCH partials into out (P pre-normalized -> plain sum).
// ---------------------------------------------------------------------------
__global__ __launch_bounds__(256) void reduce_kernel(float* __restrict__ out) {
    const size_t i = (size_t)blockIdx.x * 256 + threadIdx.x;
    float s = 0.f;
#pragma unroll
    for (int c = 0; c < KCH; c++) s += g_opart[(size_t)c * LQ * DIM + i];
    out[i] = s;
}

// ---------------------------------------------------------------------------
extern "C" void kernel_launch(void* const* d_in, const int* in_sizes, int n_in,
                              void* d_out, int out_size) {
    const float* Q = (const float*)d_in[0];
    const float* K = (const float*)d_in[1];
    const float* V = (const float*)d_in[2];
    float* out = (float*)d_out;             // [LQ, DIM]
    float* att = out + (size_t)LQ * DIM;    // [LQ, LK]

    const int smemA = (64 * STRQ + 128 * STRQ) * 2;   // 52224
    const int smemF = 98304;
    cudaFuncSetAttribute(qk_sums_kernel, cudaFuncAttributeMaxDynamicSharedMemorySize, smemA);
    cudaFuncSetAttribute(fused_kernel, cudaFuncAttributeMaxDynamicSharedMemorySize, smemF);

    prep_kernel<<<(LQ * DIM) / 256, 256>>>(Q, K, V);
    qk_sums_kernel<<<dim3(LK / 128, LQ / 64), 256, smemA>>>();
    lred_kernel<<<LQ / 256, 256>>>();
    fused_kernel<<<dim3(KCH, LQ / 64), 256, smemF>>>(att);
    reduce_kernel<<<(LQ * DIM) / 256, 256>>>(out);
}